// round 1
// baseline (speedup 1.0000x reference)
#include <cuda_runtime.h>
#include <math.h>

#define NROWS  14336      // N = BATCH * N_VARS
#define SEQL   512
#define DMODEL 512
#define NEXP   8
#define NHID   256
#define NVARS  7
#define CAP    NROWS      // max rows per expert (top-2 indices distinct)
#define MAVG   25
#define PAD    12

// ---------------- scratch (static device allocations; no cudaMalloc) --------
__device__ float g_xn  [NROWS * SEQL];          // RevIN-normalized series
__device__ float g_h   [NROWS * NHID];          // relu(xs @ gw1^T)
__device__ float g_weff[NEXP * DMODEL * SEQL];  // folded seasonal+trend weights
__device__ int   g_tkidx[NROWS * 2];
__device__ float g_tkg  [NROWS * 2];
__device__ int   g_cnt [NEXP];
__device__ float g_imp [NEXP];
__device__ float g_load[NEXP];
__device__ int   g_rows[NEXP * CAP];
__device__ float g_rowg[NEXP * CAP];

// ---------------- tiny init ----------------
__global__ void k_zero() {
    int t = threadIdx.x;
    if (t < NEXP) { g_cnt[t] = 0; g_imp[t] = 0.f; g_load[t] = 0.f; }
}

// ---------------- RevIN: per-row mean/var normalize ----------------
__global__ void __launch_bounds__(128) k_revin(const float* __restrict__ x,
                                               const float* __restrict__ rw,
                                               const float* __restrict__ rb) {
    int n = blockIdx.x;
    int t = threadIdx.x;
    const float* xr = x + (size_t)n * SEQL;
    float v[4];
    float s = 0.f, ss = 0.f;
#pragma unroll
    for (int i = 0; i < 4; i++) {
        v[i] = xr[t + 128 * i];
        s += v[i];
        ss += v[i] * v[i];
    }
#pragma unroll
    for (int o = 16; o; o >>= 1) {
        s  += __shfl_xor_sync(0xffffffffu, s, o);
        ss += __shfl_xor_sync(0xffffffffu, ss, o);
    }
    __shared__ float sh[2][4];
    int w = t >> 5;
    if ((t & 31) == 0) { sh[0][w] = s; sh[1][w] = ss; }
    __syncthreads();
    s  = sh[0][0] + sh[0][1] + sh[0][2] + sh[0][3];
    ss = sh[1][0] + sh[1][1] + sh[1][2] + sh[1][3];
    float mean = s * (1.f / SEQL);
    float var  = ss * (1.f / SEQL) - mean * mean;
    float sd   = sqrtf(var + 1e-5f);
    int vv = n % NVARS;
    float sc = rw[vv] / sd;
    float b  = rb[vv];
    float* o = g_xn + (size_t)n * SEQL;
#pragma unroll
    for (int i = 0; i < 4; i++) o[t + 128 * i] = (v[i] - mean) * sc + b;
}

// ---------------- Weff: fold moving-average operator into weights ----------
// trend = xn * M^T, M[l,j] = (1/25)*#{i in [l-12,l+12] : clamp(i,0,511)=j}
// Weff[e,p,j] = Ws[e,p,j] + sum_l (Wt-Ws)[e,p,l] * M[l,j]
__global__ void __launch_bounds__(128) k_weff(const float* __restrict__ Ws,
                                              const float* __restrict__ Wt) {
    int ep = blockIdx.x;  // e*DMODEL + p
    const float* ws = Ws + (size_t)ep * SEQL;
    const float* wt = Wt + (size_t)ep * SEQL;
    __shared__ float sD[SEQL];
    __shared__ float sW[SEQL];
    int t = threadIdx.x;
    for (int i = t; i < SEQL; i += 128) {
        float a = ws[i];
        sW[i] = a;
        sD[i] = wt[i] - a;
    }
    __syncthreads();
    float* o = g_weff + (size_t)ep * SEQL;
    for (int j = t; j < SEQL; j += 128) {
        float g = 0.f;
        if (j == 0) {
            for (int l = 0; l <= PAD; l++) g += (float)(PAD + 1 - l) * sD[l];
        } else if (j == SEQL - 1) {
            for (int l = SEQL - 1 - PAD; l < SEQL; l++)
                g += (float)(l - (SEQL - 2 - PAD)) * sD[l];
        } else {
            int lo = j - PAD; if (lo < 0) lo = 0;
            int hi = j + PAD; if (hi > SEQL - 1) hi = SEQL - 1;
            for (int l = lo; l <= hi; l++) g += sD[l];
        }
        o[j] = sW[j] + g * (1.f / MAVG);
    }
}

// ---------------- GEMM1: h = relu(x @ gw1^T)  [14336x256, K=512] ----------
__global__ void __launch_bounds__(256) k_gemm_h(const float* __restrict__ A,
                                                const float* __restrict__ B) {
    __shared__ float As[16][128];
    __shared__ float Bs[16][128];
    int m0 = blockIdx.x * 128, n0 = blockIdx.y * 128;
    int t = threadIdx.x;
    int ty = t >> 4, tx = t & 15;
    float acc[8][8] = {};
    for (int k0 = 0; k0 < SEQL; k0 += 16) {
#pragma unroll
        for (int i = 0; i < 2; i++) {
            int v = t + 256 * i;
            int m = v >> 2, kv = (v & 3) << 2;
            float4 fa = *(const float4*)&A[(size_t)(m0 + m) * SEQL + k0 + kv];
            As[kv + 0][m] = fa.x; As[kv + 1][m] = fa.y;
            As[kv + 2][m] = fa.z; As[kv + 3][m] = fa.w;
            float4 fb = *(const float4*)&B[(size_t)(n0 + m) * SEQL + k0 + kv];
            Bs[kv + 0][m] = fb.x; Bs[kv + 1][m] = fb.y;
            Bs[kv + 2][m] = fb.z; Bs[kv + 3][m] = fb.w;
        }
        __syncthreads();
#pragma unroll
        for (int k = 0; k < 16; k++) {
            float a[8], b[8];
            *(float4*)(a)     = *(const float4*)&As[k][ty * 8];
            *(float4*)(a + 4) = *(const float4*)&As[k][ty * 8 + 4];
            *(float4*)(b)     = *(const float4*)&Bs[k][tx * 8];
            *(float4*)(b + 4) = *(const float4*)&Bs[k][tx * 8 + 4];
#pragma unroll
            for (int mi = 0; mi < 8; mi++)
#pragma unroll
                for (int ni = 0; ni < 8; ni++)
                    acc[mi][ni] = fmaf(a[mi], b[ni], acc[mi][ni]);
        }
        __syncthreads();
    }
#pragma unroll
    for (int mi = 0; mi < 8; mi++) {
        int row = m0 + ty * 8 + mi;
        float* c = g_h + (size_t)row * NHID + n0 + tx * 8;
#pragma unroll
        for (int ni = 0; ni < 8; ni += 4) {
            float4 f;
            f.x = fmaxf(acc[mi][ni + 0], 0.f);
            f.y = fmaxf(acc[mi][ni + 1], 0.f);
            f.z = fmaxf(acc[mi][ni + 2], 0.f);
            f.w = fmaxf(acc[mi][ni + 3], 0.f);
            *(float4*)&c[ni] = f;
        }
    }
}

// ---------------- gating head: logits, softmax, top-2, stats ---------------
__global__ void __launch_bounds__(256) k_gate(const float* __restrict__ gw2) {
    __shared__ float sg2[NEXP * NHID];
    int t = threadIdx.x;
    for (int i = t; i < NEXP * NHID; i += 256) sg2[i] = gw2[i];
    __syncthreads();
    int w = t >> 5, lane = t & 31;
    int r = blockIdx.x * 8 + w;
    const float* h = g_h + (size_t)r * NHID;
    float acc[NEXP] = {};
    for (int k = lane; k < NHID; k += 32) {
        float hv = h[k];
#pragma unroll
        for (int e = 0; e < NEXP; e++) acc[e] = fmaf(hv, sg2[e * NHID + k], acc[e]);
    }
#pragma unroll
    for (int e = 0; e < NEXP; e++)
#pragma unroll
        for (int o = 16; o; o >>= 1) acc[e] += __shfl_xor_sync(0xffffffffu, acc[e], o);
    if (lane == 0) {
        float mx = acc[0];
#pragma unroll
        for (int e = 1; e < NEXP; e++) mx = fmaxf(mx, acc[e]);
        float p[NEXP], sum = 0.f;
#pragma unroll
        for (int e = 0; e < NEXP; e++) { p[e] = expf(acc[e] - mx); sum += p[e]; }
        float inv = 1.f / sum;
#pragma unroll
        for (int e = 0; e < NEXP; e++) p[e] *= inv;
        int i1 = 0; float v1 = p[0];
#pragma unroll
        for (int e = 1; e < NEXP; e++) if (p[e] > v1) { v1 = p[e]; i1 = e; }
        int i2 = -1; float v2 = -1.f;
#pragma unroll
        for (int e = 0; e < NEXP; e++)
            if (e != i1 && p[e] > v2) { v2 = p[e]; i2 = e; }
        float den = v1 + v2 + 1e-6f;
        float g1 = v1 / den, g2 = v2 / den;
        g_tkidx[2 * r] = i1; g_tkidx[2 * r + 1] = i2;
        g_tkg[2 * r] = g1;   g_tkg[2 * r + 1] = g2;
        atomicAdd(&g_imp[i1], g1);
        atomicAdd(&g_imp[i2], g2);
        atomicAdd(&g_load[i1], 1.f);
        atomicAdd(&g_load[i2], 1.f);
    }
}

// ---------------- build per-expert row lists (block-aggregated) ------------
__global__ void __launch_bounds__(256) k_lists() {
    __shared__ int scnt[NEXP], sbase[NEXP];
    int t = threadIdx.x;
    if (t < NEXP) scnt[t] = 0;
    __syncthreads();
    int r = blockIdx.x * 256 + t;  // 56 blocks exact
    int i1 = g_tkidx[2 * r], i2 = g_tkidx[2 * r + 1];
    int l1 = atomicAdd(&scnt[i1], 1);
    int l2 = atomicAdd(&scnt[i2], 1);
    __syncthreads();
    if (t < NEXP) sbase[t] = atomicAdd(&g_cnt[t], scnt[t]);
    __syncthreads();
    int p1 = sbase[i1] + l1, p2 = sbase[i2] + l2;
    g_rows[i1 * CAP + p1] = r; g_rowg[i1 * CAP + p1] = g_tkg[2 * r];
    g_rows[i2 * CAP + p2] = r; g_rowg[i2 * CAP + p2] = g_tkg[2 * r + 1];
}

// ---------------- expert GEMM: y += gate * (xn_rows @ Weff[e]^T) -----------
__global__ void __launch_bounds__(256) k_gemmE(float* __restrict__ y) {
    int e = blockIdx.z;
    int cnt = g_cnt[e];
    int m0 = blockIdx.x * 128;
    if (m0 >= cnt) return;
    __shared__ float As[16][128];
    __shared__ float Bs[16][128];
    __shared__ int   srow[128];
    __shared__ float sgt[128];
    int t = threadIdx.x;
    if (t < 128) {
        int m = m0 + t;
        if (m < cnt) { srow[t] = g_rows[e * CAP + m]; sgt[t] = g_rowg[e * CAP + m]; }
        else         { srow[t] = -1; sgt[t] = 0.f; }
    }
    __syncthreads();
    int n0 = blockIdx.y * 128;
    const float* B = g_weff + (size_t)e * DMODEL * SEQL;
    int ty = t >> 4, tx = t & 15;
    float acc[8][8] = {};
    for (int k0 = 0; k0 < SEQL; k0 += 16) {
#pragma unroll
        for (int i = 0; i < 2; i++) {
            int v = t + 256 * i;
            int m = v >> 2, kv = (v & 3) << 2;
            int row = srow[m];
            float4 fa = make_float4(0.f, 0.f, 0.f, 0.f);
            if (row >= 0)
                fa = *(const float4*)&g_xn[(size_t)row * SEQL + k0 + kv];
            As[kv + 0][m] = fa.x; As[kv + 1][m] = fa.y;
            As[kv + 2][m] = fa.z; As[kv + 3][m] = fa.w;
            float4 fb = *(const float4*)&B[(size_t)(n0 + m) * SEQL + k0 + kv];
            Bs[kv + 0][m] = fb.x; Bs[kv + 1][m] = fb.y;
            Bs[kv + 2][m] = fb.z; Bs[kv + 3][m] = fb.w;
        }
        __syncthreads();
#pragma unroll
        for (int k = 0; k < 16; k++) {
            float a[8], b[8];
            *(float4*)(a)     = *(const float4*)&As[k][ty * 8];
            *(float4*)(a + 4) = *(const float4*)&As[k][ty * 8 + 4];
            *(float4*)(b)     = *(const float4*)&Bs[k][tx * 8];
            *(float4*)(b + 4) = *(const float4*)&Bs[k][tx * 8 + 4];
#pragma unroll
            for (int mi = 0; mi < 8; mi++)
#pragma unroll
                for (int ni = 0; ni < 8; ni++)
                    acc[mi][ni] = fmaf(a[mi], b[ni], acc[mi][ni]);
        }
        __syncthreads();
    }
#pragma unroll
    for (int mi = 0; mi < 8; mi++) {
        int m = ty * 8 + mi;
        int row = srow[m];
        if (row < 0) continue;
        float g = sgt[m];
        float* yp = y + (size_t)row * DMODEL + n0 + tx * 8;
#pragma unroll
        for (int ni = 0; ni < 8; ni++) atomicAdd(&yp[ni], g * acc[mi][ni]);
    }
}

// ---------------- loss ----------------
__global__ void k_loss(const void* lc, float* out, int out_size) {
    float mi = 0.f, ml = 0.f;
#pragma unroll
    for (int e = 0; e < NEXP; e++) { mi += g_imp[e]; ml += g_load[e]; }
    mi *= (1.f / NEXP); ml *= (1.f / NEXP);
    float vi = 0.f, vl = 0.f;
#pragma unroll
    for (int e = 0; e < NEXP; e++) {
        float di = g_imp[e] - mi;  vi += di * di;
        float dl = g_load[e] - ml; vl += dl * dl;
    }
    vi *= (1.f / (NEXP - 1)); vl *= (1.f / (NEXP - 1));
    float cvi = vi / (mi * mi + 1e-10f);
    float cvl = vl / (ml * ml + 1e-10f);
    float coef = 1.f;
    if (lc) {
        int ib = *(const int*)lc;
        float fb = __int_as_float(ib);
        float af = fabsf(fb);
        coef = (af >= 1e-6f && af <= 1e6f) ? fb : (float)ib;
    }
    out[out_size - 1] = (cvi + cvl) * coef;
}

// ---------------- launch ----------------
extern "C" void kernel_launch(void* const* d_in, const int* in_sizes, int n_in,
                              void* d_out, int out_size) {
    const float* x   = (const float*)d_in[0];
    const float* gw1 = (const float*)d_in[1];
    const float* gw2 = (const float*)d_in[2];
    const float* Ws  = (const float*)d_in[3];
    const float* Wt  = (const float*)d_in[4];
    const float* rw  = (const float*)d_in[5];
    const float* rb  = (const float*)d_in[6];
    const void*  lc  = (n_in >= 8) ? d_in[7] : (const void*)0;
    float* out = (float*)d_out;

    k_zero<<<1, 32>>>();
    cudaMemsetAsync(d_out, 0, (size_t)out_size * sizeof(float));
    k_revin<<<NROWS, 128>>>(x, rw, rb);
    k_weff<<<NEXP * DMODEL, 128>>>(Ws, Wt);
    k_gemm_h<<<dim3(NROWS / 128, NHID / 128), 256>>>(x, gw1);
    k_gate<<<NROWS / 8, 256>>>(gw2);
    k_lists<<<NROWS / 256, 256>>>();
    k_gemmE<<<dim3(CAP / 128, DMODEL / 128, NEXP), 256>>>(out);
    k_loss<<<1, 1>>>(lc, out, out_size);
}

// round 4
// speedup vs baseline: 2.2167x; 2.2167x over previous
#include <cuda_runtime.h>
#include <stdint.h>
#include <math.h>

#define NROWS  14336
#define SEQL   512
#define DMODEL 512
#define NEXP   8
#define NHID   256
#define NVARS  7
#define CAP    NROWS
#define MAVG   25
#define PAD    12

// ---------------- scratch ----------------
__device__ float g_xn  [NROWS * SEQL];
__device__ float g_h   [NROWS * NHID];
__device__ float g_weff[NEXP * DMODEL * SEQL];
__device__ int   g_tkidx[NROWS * 2];
__device__ float g_tkg  [NROWS * 2];
__device__ int   g_cnt [NEXP];
__device__ float g_imp [NEXP];
__device__ float g_load[NEXP];
__device__ int   g_rows[NEXP * CAP];
__device__ float g_rowg[NEXP * CAP];

// ---------------- helpers ----------------
__device__ __forceinline__ void cp16(float* dst, const float* src) {
    uint32_t d = (uint32_t)__cvta_generic_to_shared(dst);
    asm volatile("cp.async.cg.shared.global [%0], [%1], 16;\n" :: "r"(d), "l"(src));
}
__device__ __forceinline__ void cp16z(float* dst, const float* src, int pred) {
    uint32_t d = (uint32_t)__cvta_generic_to_shared(dst);
    int bytes = pred ? 16 : 0;
    asm volatile("cp.async.cg.shared.global [%0], [%1], 16, %2;\n"
                 :: "r"(d), "l"(src), "r"(bytes));
}
#define CP_COMMIT() asm volatile("cp.async.commit_group;\n")
#define CP_WAIT1()  asm volatile("cp.async.wait_group 1;\n")
#define CP_WAIT0()  asm volatile("cp.async.wait_group 0;\n")

__device__ __forceinline__ uint32_t f2tf(float v) {
    uint32_t r; asm("cvt.rna.tf32.f32 %0, %1;" : "=r"(r) : "f"(v)); return r;
}
__device__ __forceinline__ void split_tf(float v, uint32_t& hi, uint32_t& lo) {
    uint32_t h; asm("cvt.rna.tf32.f32 %0, %1;" : "=r"(h) : "f"(v));
    float r = v - __uint_as_float(h);
    uint32_t l; asm("cvt.rna.tf32.f32 %0, %1;" : "=r"(l) : "f"(r));
    hi = h; lo = l;
}
__device__ __forceinline__ void mma8(float* c, const uint32_t* a, const uint32_t* b) {
    asm volatile(
        "mma.sync.aligned.m16n8k8.row.col.f32.tf32.tf32.f32 "
        "{%0,%1,%2,%3}, {%4,%5,%6,%7}, {%8,%9}, {%0,%1,%2,%3};"
        : "+f"(c[0]), "+f"(c[1]), "+f"(c[2]), "+f"(c[3])
        : "r"(a[0]), "r"(a[1]), "r"(a[2]), "r"(a[3]), "r"(b[0]), "r"(b[1]));
}

// ---------------- tiny init ----------------
__global__ void k_zero() {
    int t = threadIdx.x;
    if (t < NEXP) { g_cnt[t] = 0; g_imp[t] = 0.f; g_load[t] = 0.f; }
}

// ---------------- RevIN ----------------
__global__ void __launch_bounds__(128) k_revin(const float* __restrict__ x,
                                               const float* __restrict__ rw,
                                               const float* __restrict__ rb) {
    int n = blockIdx.x;
    int t = threadIdx.x;
    const float* xr = x + (size_t)n * SEQL;
    float v[4];
    float s = 0.f, ss = 0.f;
#pragma unroll
    for (int i = 0; i < 4; i++) {
        v[i] = xr[t + 128 * i];
        s += v[i]; ss += v[i] * v[i];
    }
#pragma unroll
    for (int o = 16; o; o >>= 1) {
        s  += __shfl_xor_sync(0xffffffffu, s, o);
        ss += __shfl_xor_sync(0xffffffffu, ss, o);
    }
    __shared__ float sh[2][4];
    int w = t >> 5;
    if ((t & 31) == 0) { sh[0][w] = s; sh[1][w] = ss; }
    __syncthreads();
    s  = sh[0][0] + sh[0][1] + sh[0][2] + sh[0][3];
    ss = sh[1][0] + sh[1][1] + sh[1][2] + sh[1][3];
    float mean = s * (1.f / SEQL);
    float var  = ss * (1.f / SEQL) - mean * mean;
    float sd   = sqrtf(var + 1e-5f);
    int vv = n % NVARS;
    float sc = rw[vv] / sd;
    float b  = rb[vv];
    float* o = g_xn + (size_t)n * SEQL;
#pragma unroll
    for (int i = 0; i < 4; i++) o[t + 128 * i] = (v[i] - mean) * sc + b;
}

// ---------------- Weff fold ----------------
__global__ void __launch_bounds__(128) k_weff(const float* __restrict__ Ws,
                                              const float* __restrict__ Wt) {
    int ep = blockIdx.x;
    const float* ws = Ws + (size_t)ep * SEQL;
    const float* wt = Wt + (size_t)ep * SEQL;
    __shared__ float sD[SEQL];
    __shared__ float sW[SEQL];
    int t = threadIdx.x;
    for (int i = t; i < SEQL; i += 128) {
        float a = ws[i];
        sW[i] = a;
        sD[i] = wt[i] - a;
    }
    __syncthreads();
    float* o = g_weff + (size_t)ep * SEQL;
    for (int j = t; j < SEQL; j += 128) {
        float g = 0.f;
        if (j == 0) {
            for (int l = 0; l <= PAD; l++) g += (float)(PAD + 1 - l) * sD[l];
        } else if (j == SEQL - 1) {
            for (int l = SEQL - 1 - PAD; l < SEQL; l++)
                g += (float)(l - (SEQL - 2 - PAD)) * sD[l];
        } else {
            int lo = j - PAD; if (lo < 0) lo = 0;
            int hi = j + PAD; if (hi > SEQL - 1) hi = SEQL - 1;
            for (int l = lo; l <= hi; l++) g += sD[l];
        }
        o[j] = sW[j] + g * (1.f / MAVG);
    }
}

// ---------------- GEMM1 (3xTF32 split): h = relu(x @ gw1^T) ----------------
__global__ void __launch_bounds__(256) k_gemm_h(const float* __restrict__ A,
                                                const float* __restrict__ B) {
    __shared__ float As[2][128 * 16];
    __shared__ float Bs[2][128 * 16];
    int m0 = blockIdx.x * 128, n0 = blockIdx.y * 128;
    int t = threadIdx.x;

    int lane = t & 31, warp = t >> 5;
    int wm = warp >> 2, wn = warp & 3;
    int lr = lane >> 2, lc = lane & 3;
    int sx = (lr & 6) << 1;

    float acc[4][4][4];
#pragma unroll
    for (int i = 0; i < 4; i++)
#pragma unroll
        for (int j = 0; j < 4; j++)
#pragma unroll
            for (int q = 0; q < 4; q++) acc[i][j][q] = 0.f;

#define LOADHB(buf, kt)                                                        \
    {                                                                          \
        _Pragma("unroll")                                                      \
        for (int i = 0; i < 2; i++) {                                          \
            int c = i * 256 + t;                                               \
            int row = c >> 2, ch = c & 3;                                      \
            int off = row * 16 + ((ch * 4) ^ ((row & 6) << 1));                \
            cp16(&As[buf][off], A + (size_t)(m0 + row) * SEQL + (kt) * 16 + ch * 4); \
            cp16(&Bs[buf][off], B + (size_t)(n0 + row) * SEQL + (kt) * 16 + ch * 4); \
        }                                                                      \
    }

    LOADHB(0, 0);
    CP_COMMIT();

    const int KT = SEQL / 16;
    for (int kt = 0; kt < KT; kt++) {
        int cur = kt & 1;
        if (kt + 1 < KT) {
            LOADHB((kt + 1) & 1, kt + 1);
            CP_COMMIT();
            CP_WAIT1();
        } else {
            CP_WAIT0();
        }
        __syncthreads();
        const float* a_s = As[cur];
        const float* b_s = Bs[cur];
#pragma unroll
        for (int k8 = 0; k8 < 16; k8 += 8) {
            int k0 = (k8 + lc) ^ sx;
            int k1 = (k8 + lc + 4) ^ sx;
            uint32_t ah[4][4], al[4][4], bh[4][2], bl[4][2];
#pragma unroll
            for (int mi = 0; mi < 4; mi++) {
                int mb = (wm * 64 + mi * 16 + lr) * 16;
                split_tf(a_s[mb + k0],       ah[mi][0], al[mi][0]);
                split_tf(a_s[mb + 128 + k0], ah[mi][1], al[mi][1]);
                split_tf(a_s[mb + k1],       ah[mi][2], al[mi][2]);
                split_tf(a_s[mb + 128 + k1], ah[mi][3], al[mi][3]);
            }
#pragma unroll
            for (int ni = 0; ni < 4; ni++) {
                int nb = (wn * 32 + ni * 8 + lr) * 16;
                split_tf(b_s[nb + k0], bh[ni][0], bl[ni][0]);
                split_tf(b_s[nb + k1], bh[ni][1], bl[ni][1]);
            }
#pragma unroll
            for (int mi = 0; mi < 4; mi++)
#pragma unroll
                for (int ni = 0; ni < 4; ni++) {
                    mma8(acc[mi][ni], ah[mi], bh[ni]);
                    mma8(acc[mi][ni], al[mi], bh[ni]);
                    mma8(acc[mi][ni], ah[mi], bl[ni]);
                }
        }
        __syncthreads();
    }
#undef LOADHB

#pragma unroll
    for (int mi = 0; mi < 4; mi++) {
        int row = m0 + wm * 64 + mi * 16 + lr;
#pragma unroll
        for (int ni = 0; ni < 4; ni++) {
            int col = n0 + wn * 32 + ni * 8 + lc * 2;
            float2 v0 = make_float2(fmaxf(acc[mi][ni][0], 0.f), fmaxf(acc[mi][ni][1], 0.f));
            float2 v1 = make_float2(fmaxf(acc[mi][ni][2], 0.f), fmaxf(acc[mi][ni][3], 0.f));
            *(float2*)&g_h[(size_t)row * NHID + col]       = v0;
            *(float2*)&g_h[(size_t)(row + 8) * NHID + col] = v1;
        }
    }
}

// ---------------- gating head ----------------
__global__ void __launch_bounds__(256) k_gate(const float* __restrict__ gw2) {
    __shared__ float sg2[NEXP * NHID];
    int t = threadIdx.x;
    for (int i = t; i < NEXP * NHID; i += 256) sg2[i] = gw2[i];
    __syncthreads();
    int w = t >> 5, lane = t & 31;
    int r = blockIdx.x * 8 + w;
    const float* h = g_h + (size_t)r * NHID;
    float acc[NEXP] = {};
    for (int k = lane; k < NHID; k += 32) {
        float hv = h[k];
#pragma unroll
        for (int e = 0; e < NEXP; e++) acc[e] = fmaf(hv, sg2[e * NHID + k], acc[e]);
    }
#pragma unroll
    for (int e = 0; e < NEXP; e++)
#pragma unroll
        for (int o = 16; o; o >>= 1) acc[e] += __shfl_xor_sync(0xffffffffu, acc[e], o);
    if (lane == 0) {
        float mx = acc[0];
#pragma unroll
        for (int e = 1; e < NEXP; e++) mx = fmaxf(mx, acc[e]);
        float p[NEXP], sum = 0.f;
#pragma unroll
        for (int e = 0; e < NEXP; e++) { p[e] = expf(acc[e] - mx); sum += p[e]; }
        float inv = 1.f / sum;
#pragma unroll
        for (int e = 0; e < NEXP; e++) p[e] *= inv;
        int i1 = 0; float v1 = p[0];
#pragma unroll
        for (int e = 1; e < NEXP; e++) if (p[e] > v1) { v1 = p[e]; i1 = e; }
        int i2 = -1; float v2 = -1.f;
#pragma unroll
        for (int e = 0; e < NEXP; e++)
            if (e != i1 && p[e] > v2) { v2 = p[e]; i2 = e; }
        float den = v1 + v2 + 1e-6f;
        float g1 = v1 / den, g2 = v2 / den;
        g_tkidx[2 * r] = i1; g_tkidx[2 * r + 1] = i2;
        g_tkg[2 * r] = g1;   g_tkg[2 * r + 1] = g2;
        atomicAdd(&g_imp[i1], g1);
        atomicAdd(&g_imp[i2], g2);
        atomicAdd(&g_load[i1], 1.f);
        atomicAdd(&g_load[i2], 1.f);
    }
}

// ---------------- per-expert row lists ----------------
__global__ void __launch_bounds__(256) k_lists() {
    __shared__ int scnt[NEXP], sbase[NEXP];
    int t = threadIdx.x;
    if (t < NEXP) scnt[t] = 0;
    __syncthreads();
    int r = blockIdx.x * 256 + t;
    int i1 = g_tkidx[2 * r], i2 = g_tkidx[2 * r + 1];
    int l1 = atomicAdd(&scnt[i1], 1);
    int l2 = atomicAdd(&scnt[i2], 1);
    __syncthreads();
    if (t < NEXP) sbase[t] = atomicAdd(&g_cnt[t], scnt[t]);
    __syncthreads();
    int p1 = sbase[i1] + l1, p2 = sbase[i2] + l2;
    g_rows[i1 * CAP + p1] = r; g_rowg[i1 * CAP + p1] = g_tkg[2 * r];
    g_rows[i2 * CAP + p2] = r; g_rowg[i2 * CAP + p2] = g_tkg[2 * r + 1];
}

// ---------------- expert GEMM (tf32): y += gate * (xn_rows @ Weff[e]^T) ----
__global__ void __launch_bounds__(256) k_gemmE(float* __restrict__ y) {
    int e = blockIdx.z;
    int cnt = g_cnt[e];
    int m0 = blockIdx.x * 128;
    if (m0 >= cnt) return;
    __shared__ float As[2][128 * 16];
    __shared__ float Bs[2][128 * 16];
    __shared__ int   srow[128];
    __shared__ float sgt[128];
    int t = threadIdx.x;
    if (t < 128) {
        int m = m0 + t;
        srow[t] = (m < cnt) ? g_rows[e * CAP + m] : -1;
        sgt[t]  = (m < cnt) ? g_rowg[e * CAP + m] : 0.f;
    }
    __syncthreads();
    int n0 = blockIdx.y * 128;
    const float* B = g_weff + (size_t)e * DMODEL * SEQL;

    int lane = t & 31, warp = t >> 5;
    int wm = warp >> 2, wn = warp & 3;
    int lr = lane >> 2, lc = lane & 3;
    int sx = (lr & 6) << 1;

    float acc[4][4][4];
#pragma unroll
    for (int i = 0; i < 4; i++)
#pragma unroll
        for (int j = 0; j < 4; j++)
#pragma unroll
            for (int q = 0; q < 4; q++) acc[i][j][q] = 0.f;

#define LOADE(buf, kt)                                                         \
    {                                                                          \
        _Pragma("unroll")                                                      \
        for (int i = 0; i < 2; i++) {                                          \
            int c = i * 256 + t;                                               \
            int row = c >> 2, ch = c & 3;                                      \
            int off = row * 16 + ((ch * 4) ^ ((row & 6) << 1));                \
            int gr = srow[row];                                                \
            int grs = gr < 0 ? 0 : gr;                                         \
            cp16z(&As[buf][off], g_xn + (size_t)grs * SEQL + (kt) * 16 + ch * 4, gr >= 0); \
            cp16(&Bs[buf][off], B + (size_t)(n0 + row) * SEQL + (kt) * 16 + ch * 4); \
        }                                                                      \
    }

    LOADE(0, 0);
    CP_COMMIT();

    const int KT = SEQL / 16;
    for (int kt = 0; kt < KT; kt++) {
        int cur = kt & 1;
        if (kt + 1 < KT) {
            LOADE((kt + 1) & 1, kt + 1);
            CP_COMMIT();
            CP_WAIT1();
        } else {
            CP_WAIT0();
        }
        __syncthreads();
        const float* a_s = As[cur];
        const float* b_s = Bs[cur];
#pragma unroll
        for (int k8 = 0; k8 < 16; k8 += 8) {
            int k0 = (k8 + lc) ^ sx;
            int k1 = (k8 + lc + 4) ^ sx;
            uint32_t a[4][4], b[4][2];
#pragma unroll
            for (int mi = 0; mi < 4; mi++) {
                int mb = (wm * 64 + mi * 16 + lr) * 16;
                a[mi][0] = f2tf(a_s[mb + k0]);
                a[mi][1] = f2tf(a_s[mb + 128 + k0]);
                a[mi][2] = f2tf(a_s[mb + k1]);
                a[mi][3] = f2tf(a_s[mb + 128 + k1]);
            }
#pragma unroll
            for (int ni = 0; ni < 4; ni++) {
                int nb = (wn * 32 + ni * 8 + lr) * 16;
                b[ni][0] = f2tf(b_s[nb + k0]);
                b[ni][1] = f2tf(b_s[nb + k1]);
            }
#pragma unroll
            for (int mi = 0; mi < 4; mi++)
#pragma unroll
                for (int ni = 0; ni < 4; ni++)
                    mma8(acc[mi][ni], a[mi], b[ni]);
        }
        __syncthreads();
    }
#undef LOADE

#pragma unroll
    for (int mi = 0; mi < 4; mi++) {
        int ml = wm * 64 + mi * 16 + lr;
        int r0 = srow[ml], r1 = srow[ml + 8];
        float g0 = sgt[ml], g1 = sgt[ml + 8];
#pragma unroll
        for (int ni = 0; ni < 4; ni++) {
            int col = n0 + wn * 32 + ni * 8 + lc * 2;
            if (r0 >= 0) {
                atomicAdd(&y[(size_t)r0 * DMODEL + col],     g0 * acc[mi][ni][0]);
                atomicAdd(&y[(size_t)r0 * DMODEL + col + 1], g0 * acc[mi][ni][1]);
            }
            if (r1 >= 0) {
                atomicAdd(&y[(size_t)r1 * DMODEL + col],     g1 * acc[mi][ni][2]);
                atomicAdd(&y[(size_t)r1 * DMODEL + col + 1], g1 * acc[mi][ni][3]);
            }
        }
    }
}

// ---------------- loss ----------------
__global__ void k_loss(const void* lc, float* out, int out_size) {
    float mi = 0.f, ml = 0.f;
#pragma unroll
    for (int e = 0; e < NEXP; e++) { mi += g_imp[e]; ml += g_load[e]; }
    mi *= (1.f / NEXP); ml *= (1.f / NEXP);
    float vi = 0.f, vl = 0.f;
#pragma unroll
    for (int e = 0; e < NEXP; e++) {
        float di = g_imp[e] - mi;  vi += di * di;
        float dl = g_load[e] - ml; vl += dl * dl;
    }
    vi *= (1.f / (NEXP - 1)); vl *= (1.f / (NEXP - 1));
    float cvi = vi / (mi * mi + 1e-10f);
    float cvl = vl / (ml * ml + 1e-10f);
    float coef = 1.f;
    if (lc) {
        int ib = *(const int*)lc;
        float fb = __int_as_float(ib);
        float af = fabsf(fb);
        coef = (af >= 1e-6f && af <= 1e6f) ? fb : (float)ib;
    }
    out[out_size - 1] = (cvi + cvl) * coef;
}

// ---------------- launch ----------------
extern "C" void kernel_launch(void* const* d_in, const int* in_sizes, int n_in,
                              void* d_out, int out_size) {
    const float* x   = (const float*)d_in[0];
    const float* gw1 = (const float*)d_in[1];
    const float* gw2 = (const float*)d_in[2];
    const float* Ws  = (const float*)d_in[3];
    const float* Wt  = (const float*)d_in[4];
    const float* rw  = (const float*)d_in[5];
    const float* rb  = (const float*)d_in[6];
    const void*  lc  = (n_in >= 8) ? d_in[7] : (const void*)0;
    float* out = (float*)d_out;

    k_zero<<<1, 32>>>();
    cudaMemsetAsync(d_out, 0, (size_t)out_size * sizeof(float));
    k_revin<<<NROWS, 128>>>(x, rw, rb);
    k_weff<<<NEXP * DMODEL, 128>>>(Ws, Wt);
    k_gemm_h<<<dim3(NROWS / 128, NHID / 128), 256>>>(x, gw1);
    k_gate<<<NROWS / 8, 256>>>(gw2);
    k_lists<<<NROWS / 256, 256>>>();
    k_gemmE<<<dim3(CAP / 128, DMODEL / 128, NEXP), 256>>>(out);
    k_loss<<<1, 1>>>(lc, out, out_size);
}

// round 5
// speedup vs baseline: 2.2879x; 1.0322x over previous
#include <cuda_runtime.h>
#include <stdint.h>
#include <math.h>

#define NROWS  14336
#define SEQL   512
#define DMODEL 512
#define NEXP   8
#define NHID   256
#define NVARS  7
#define CAP    NROWS
#define MAVG   25
#define PAD    12

// ---------------- scratch ----------------
__device__ float g_xn  [NROWS * SEQL];
__device__ float g_h   [NROWS * NHID];
__device__ float g_weff[NEXP * DMODEL * SEQL];
__device__ int   g_tkidx[NROWS * 2];
__device__ float g_tkg  [NROWS * 2];
__device__ int   g_cnt [NEXP];
__device__ float g_imp [NEXP];
__device__ float g_load[NEXP];
__device__ int   g_rows[NEXP * CAP];
__device__ float g_rowg[NEXP * CAP];

// ---------------- helpers ----------------
__device__ __forceinline__ void cp16(float* dst, const float* src) {
    uint32_t d = (uint32_t)__cvta_generic_to_shared(dst);
    asm volatile("cp.async.cg.shared.global [%0], [%1], 16;\n" :: "r"(d), "l"(src));
}
__device__ __forceinline__ void cp16z(float* dst, const float* src, int pred) {
    uint32_t d = (uint32_t)__cvta_generic_to_shared(dst);
    int bytes = pred ? 16 : 0;
    asm volatile("cp.async.cg.shared.global [%0], [%1], 16, %2;\n"
                 :: "r"(d), "l"(src), "r"(bytes));
}
#define CP_COMMIT() asm volatile("cp.async.commit_group;\n")
#define CP_WAIT1()  asm volatile("cp.async.wait_group 1;\n")
#define CP_WAIT0()  asm volatile("cp.async.wait_group 0;\n")

__device__ __forceinline__ uint32_t f2tf(float v) {
    uint32_t r; asm("cvt.rna.tf32.f32 %0, %1;" : "=r"(r) : "f"(v)); return r;
}
__device__ __forceinline__ void split_tf(float v, uint32_t& hi, uint32_t& lo) {
    uint32_t h; asm("cvt.rna.tf32.f32 %0, %1;" : "=r"(h) : "f"(v));
    float r = v - __uint_as_float(h);
    uint32_t l; asm("cvt.rna.tf32.f32 %0, %1;" : "=r"(l) : "f"(r));
    hi = h; lo = l;
}
__device__ __forceinline__ void mma8(float* c, const uint32_t* a, const uint32_t* b) {
    asm volatile(
        "mma.sync.aligned.m16n8k8.row.col.f32.tf32.tf32.f32 "
        "{%0,%1,%2,%3}, {%4,%5,%6,%7}, {%8,%9}, {%0,%1,%2,%3};"
        : "+f"(c[0]), "+f"(c[1]), "+f"(c[2]), "+f"(c[3])
        : "r"(a[0]), "r"(a[1]), "r"(a[2]), "r"(a[3]), "r"(b[0]), "r"(b[1]));
}

// ---------------- tiny init ----------------
__global__ void k_zero() {
    int t = threadIdx.x;
    if (t < NEXP) { g_cnt[t] = 0; g_imp[t] = 0.f; g_load[t] = 0.f; }
}

// ---------------- RevIN ----------------
__global__ void __launch_bounds__(128) k_revin(const float* __restrict__ x,
                                               const float* __restrict__ rw,
                                               const float* __restrict__ rb) {
    int n = blockIdx.x;
    int t = threadIdx.x;
    const float* xr = x + (size_t)n * SEQL;
    float v[4];
    float s = 0.f, ss = 0.f;
#pragma unroll
    for (int i = 0; i < 4; i++) {
        v[i] = xr[t + 128 * i];
        s += v[i]; ss += v[i] * v[i];
    }
#pragma unroll
    for (int o = 16; o; o >>= 1) {
        s  += __shfl_xor_sync(0xffffffffu, s, o);
        ss += __shfl_xor_sync(0xffffffffu, ss, o);
    }
    __shared__ float sh[2][4];
    int w = t >> 5;
    if ((t & 31) == 0) { sh[0][w] = s; sh[1][w] = ss; }
    __syncthreads();
    s  = sh[0][0] + sh[0][1] + sh[0][2] + sh[0][3];
    ss = sh[1][0] + sh[1][1] + sh[1][2] + sh[1][3];
    float mean = s * (1.f / SEQL);
    float var  = ss * (1.f / SEQL) - mean * mean;
    float sd   = sqrtf(var + 1e-5f);
    int vv = n % NVARS;
    float sc = rw[vv] / sd;
    float b  = rb[vv];
    float* o = g_xn + (size_t)n * SEQL;
#pragma unroll
    for (int i = 0; i < 4; i++) o[t + 128 * i] = (v[i] - mean) * sc + b;
}

// ---------------- Weff fold ----------------
__global__ void __launch_bounds__(128) k_weff(const float* __restrict__ Ws,
                                              const float* __restrict__ Wt) {
    int ep = blockIdx.x;
    const float* ws = Ws + (size_t)ep * SEQL;
    const float* wt = Wt + (size_t)ep * SEQL;
    __shared__ float sD[SEQL];
    __shared__ float sW[SEQL];
    int t = threadIdx.x;
    for (int i = t; i < SEQL; i += 128) {
        float a = ws[i];
        sW[i] = a;
        sD[i] = wt[i] - a;
    }
    __syncthreads();
    float* o = g_weff + (size_t)ep * SEQL;
    for (int j = t; j < SEQL; j += 128) {
        float g = 0.f;
        if (j == 0) {
            for (int l = 0; l <= PAD; l++) g += (float)(PAD + 1 - l) * sD[l];
        } else if (j == SEQL - 1) {
            for (int l = SEQL - 1 - PAD; l < SEQL; l++)
                g += (float)(l - (SEQL - 2 - PAD)) * sD[l];
        } else {
            int lo = j - PAD; if (lo < 0) lo = 0;
            int hi = j + PAD; if (hi > SEQL - 1) hi = SEQL - 1;
            for (int l = lo; l <= hi; l++) g += sD[l];
        }
        o[j] = sW[j] + g * (1.f / MAVG);
    }
}

// ---------------- GEMM1 (3xTF32 split): h = relu(x @ gw1^T) ----------------
__global__ void __launch_bounds__(256, 2) k_gemm_h(const float* __restrict__ A,
                                                   const float* __restrict__ B) {
    __shared__ float As[2][128 * 16];
    __shared__ float Bs[2][128 * 16];
    int m0 = blockIdx.x * 128, n0 = blockIdx.y * 128;
    int t = threadIdx.x;

    int lane = t & 31, warp = t >> 5;
    int wm = warp >> 2, wn = warp & 3;
    int lr = lane >> 2, lc = lane & 3;
    int sx = (lr & 6) << 1;

    float acc[4][4][4];
#pragma unroll
    for (int i = 0; i < 4; i++)
#pragma unroll
        for (int j = 0; j < 4; j++)
#pragma unroll
            for (int q = 0; q < 4; q++) acc[i][j][q] = 0.f;

#define LOADHB(buf, kt)                                                        \
    {                                                                          \
        _Pragma("unroll")                                                      \
        for (int i = 0; i < 2; i++) {                                          \
            int c = i * 256 + t;                                               \
            int row = c >> 2, ch = c & 3;                                      \
            int off = row * 16 + ((ch * 4) ^ ((row & 6) << 1));                \
            cp16(&As[buf][off], A + (size_t)(m0 + row) * SEQL + (kt) * 16 + ch * 4); \
            cp16(&Bs[buf][off], B + (size_t)(n0 + row) * SEQL + (kt) * 16 + ch * 4); \
        }                                                                      \
    }

    LOADHB(0, 0);
    CP_COMMIT();

    const int KT = SEQL / 16;
    for (int kt = 0; kt < KT; kt++) {
        int cur = kt & 1;
        if (kt + 1 < KT) {
            LOADHB((kt + 1) & 1, kt + 1);
            CP_COMMIT();
            CP_WAIT1();
        } else {
            CP_WAIT0();
        }
        __syncthreads();
        const float* a_s = As[cur];
        const float* b_s = Bs[cur];
#pragma unroll
        for (int k8 = 0; k8 < 16; k8 += 8) {
            int k0 = (k8 + lc) ^ sx;
            int k1 = (k8 + lc + 4) ^ sx;
            // B fragments first (16 regs live), then A per-mi (8 regs live)
            uint32_t bh[4][2], bl[4][2];
#pragma unroll
            for (int ni = 0; ni < 4; ni++) {
                int nb = (wn * 32 + ni * 8 + lr) * 16;
                split_tf(b_s[nb + k0], bh[ni][0], bl[ni][0]);
                split_tf(b_s[nb + k1], bh[ni][1], bl[ni][1]);
            }
#pragma unroll
            for (int mi = 0; mi < 4; mi++) {
                uint32_t ah[4], al[4];
                int mb = (wm * 64 + mi * 16 + lr) * 16;
                split_tf(a_s[mb + k0],       ah[0], al[0]);
                split_tf(a_s[mb + 128 + k0], ah[1], al[1]);
                split_tf(a_s[mb + k1],       ah[2], al[2]);
                split_tf(a_s[mb + 128 + k1], ah[3], al[3]);
#pragma unroll
                for (int ni = 0; ni < 4; ni++) {
                    mma8(acc[mi][ni], ah, bh[ni]);
                    mma8(acc[mi][ni], al, bh[ni]);
                    mma8(acc[mi][ni], ah, bl[ni]);
                }
            }
        }
        __syncthreads();
    }
#undef LOADHB

#pragma unroll
    for (int mi = 0; mi < 4; mi++) {
        int row = m0 + wm * 64 + mi * 16 + lr;
#pragma unroll
        for (int ni = 0; ni < 4; ni++) {
            int col = n0 + wn * 32 + ni * 8 + lc * 2;
            float2 v0 = make_float2(fmaxf(acc[mi][ni][0], 0.f), fmaxf(acc[mi][ni][1], 0.f));
            float2 v1 = make_float2(fmaxf(acc[mi][ni][2], 0.f), fmaxf(acc[mi][ni][3], 0.f));
            *(float2*)&g_h[(size_t)row * NHID + col]       = v0;
            *(float2*)&g_h[(size_t)(row + 8) * NHID + col] = v1;
        }
    }
}

// ---------------- gating head ----------------
__global__ void __launch_bounds__(256) k_gate(const float* __restrict__ gw2) {
    __shared__ float sg2[NEXP * NHID];
    int t = threadIdx.x;
    for (int i = t; i < NEXP * NHID; i += 256) sg2[i] = gw2[i];
    __syncthreads();
    int w = t >> 5, lane = t & 31;
    int r = blockIdx.x * 8 + w;
    const float* h = g_h + (size_t)r * NHID;
    float acc[NEXP] = {};
    for (int k = lane; k < NHID; k += 32) {
        float hv = h[k];
#pragma unroll
        for (int e = 0; e < NEXP; e++) acc[e] = fmaf(hv, sg2[e * NHID + k], acc[e]);
    }
#pragma unroll
    for (int e = 0; e < NEXP; e++)
#pragma unroll
        for (int o = 16; o; o >>= 1) acc[e] += __shfl_xor_sync(0xffffffffu, acc[e], o);
    if (lane == 0) {
        float mx = acc[0];
#pragma unroll
        for (int e = 1; e < NEXP; e++) mx = fmaxf(mx, acc[e]);
        float p[NEXP], sum = 0.f;
#pragma unroll
        for (int e = 0; e < NEXP; e++) { p[e] = expf(acc[e] - mx); sum += p[e]; }
        float inv = 1.f / sum;
#pragma unroll
        for (int e = 0; e < NEXP; e++) p[e] *= inv;
        int i1 = 0; float v1 = p[0];
#pragma unroll
        for (int e = 1; e < NEXP; e++) if (p[e] > v1) { v1 = p[e]; i1 = e; }
        int i2 = -1; float v2 = -1.f;
#pragma unroll
        for (int e = 0; e < NEXP; e++)
            if (e != i1 && p[e] > v2) { v2 = p[e]; i2 = e; }
        float den = v1 + v2 + 1e-6f;
        float g1 = v1 / den, g2 = v2 / den;
        g_tkidx[2 * r] = i1; g_tkidx[2 * r + 1] = i2;
        g_tkg[2 * r] = g1;   g_tkg[2 * r + 1] = g2;
        atomicAdd(&g_imp[i1], g1);
        atomicAdd(&g_imp[i2], g2);
        atomicAdd(&g_load[i1], 1.f);
        atomicAdd(&g_load[i2], 1.f);
    }
}

// ---------------- per-expert row lists ----------------
__global__ void __launch_bounds__(256) k_lists() {
    __shared__ int scnt[NEXP], sbase[NEXP];
    int t = threadIdx.x;
    if (t < NEXP) scnt[t] = 0;
    __syncthreads();
    int r = blockIdx.x * 256 + t;
    int i1 = g_tkidx[2 * r], i2 = g_tkidx[2 * r + 1];
    int l1 = atomicAdd(&scnt[i1], 1);
    int l2 = atomicAdd(&scnt[i2], 1);
    __syncthreads();
    if (t < NEXP) sbase[t] = atomicAdd(&g_cnt[t], scnt[t]);
    __syncthreads();
    int p1 = sbase[i1] + l1, p2 = sbase[i2] + l2;
    g_rows[i1 * CAP + p1] = r; g_rowg[i1 * CAP + p1] = g_tkg[2 * r];
    g_rows[i2 * CAP + p2] = r; g_rowg[i2 * CAP + p2] = g_tkg[2 * r + 1];
}

// ---------------- expert GEMM (tf32): y += gate * (xn_rows @ Weff[e]^T) ----
__global__ void __launch_bounds__(256, 2) k_gemmE(float* __restrict__ y) {
    int e = blockIdx.z;
    int cnt = g_cnt[e];
    int m0 = blockIdx.x * 128;
    if (m0 >= cnt) return;
    __shared__ float As[2][128 * 16];
    __shared__ float Bs[2][128 * 16];
    __shared__ int   srow[128];
    __shared__ float sgt[128];
    int t = threadIdx.x;
    if (t < 128) {
        int m = m0 + t;
        srow[t] = (m < cnt) ? g_rows[e * CAP + m] : -1;
        sgt[t]  = (m < cnt) ? g_rowg[e * CAP + m] : 0.f;
    }
    __syncthreads();
    int n0 = blockIdx.y * 128;
    const float* B = g_weff + (size_t)e * DMODEL * SEQL;

    int lane = t & 31, warp = t >> 5;
    int wm = warp >> 2, wn = warp & 3;
    int lr = lane >> 2, lc = lane & 3;
    int sx = (lr & 6) << 1;

    float acc[4][4][4];
#pragma unroll
    for (int i = 0; i < 4; i++)
#pragma unroll
        for (int j = 0; j < 4; j++)
#pragma unroll
            for (int q = 0; q < 4; q++) acc[i][j][q] = 0.f;

#define LOADE(buf, kt)                                                         \
    {                                                                          \
        _Pragma("unroll")                                                      \
        for (int i = 0; i < 2; i++) {                                          \
            int c = i * 256 + t;                                               \
            int row = c >> 2, ch = c & 3;                                      \
            int off = row * 16 + ((ch * 4) ^ ((row & 6) << 1));                \
            int gr = srow[row];                                                \
            int grs = gr < 0 ? 0 : gr;                                         \
            cp16z(&As[buf][off], g_xn + (size_t)grs * SEQL + (kt) * 16 + ch * 4, gr >= 0); \
            cp16(&Bs[buf][off], B + (size_t)(n0 + row) * SEQL + (kt) * 16 + ch * 4); \
        }                                                                      \
    }

    LOADE(0, 0);
    CP_COMMIT();

    const int KT = SEQL / 16;
    for (int kt = 0; kt < KT; kt++) {
        int cur = kt & 1;
        if (kt + 1 < KT) {
            LOADE((kt + 1) & 1, kt + 1);
            CP_COMMIT();
            CP_WAIT1();
        } else {
            CP_WAIT0();
        }
        __syncthreads();
        const float* a_s = As[cur];
        const float* b_s = Bs[cur];
#pragma unroll
        for (int k8 = 0; k8 < 16; k8 += 8) {
            int k0 = (k8 + lc) ^ sx;
            int k1 = (k8 + lc + 4) ^ sx;
            uint32_t a[4][4], b[4][2];
#pragma unroll
            for (int mi = 0; mi < 4; mi++) {
                int mb = (wm * 64 + mi * 16 + lr) * 16;
                a[mi][0] = f2tf(a_s[mb + k0]);
                a[mi][1] = f2tf(a_s[mb + 128 + k0]);
                a[mi][2] = f2tf(a_s[mb + k1]);
                a[mi][3] = f2tf(a_s[mb + 128 + k1]);
            }
#pragma unroll
            for (int ni = 0; ni < 4; ni++) {
                int nb = (wn * 32 + ni * 8 + lr) * 16;
                b[ni][0] = f2tf(b_s[nb + k0]);
                b[ni][1] = f2tf(b_s[nb + k1]);
            }
#pragma unroll
            for (int mi = 0; mi < 4; mi++)
#pragma unroll
                for (int ni = 0; ni < 4; ni++)
                    mma8(acc[mi][ni], a[mi], b[ni]);
        }
        __syncthreads();
    }
#undef LOADE

#pragma unroll
    for (int mi = 0; mi < 4; mi++) {
        int ml = wm * 64 + mi * 16 + lr;
        int r0 = srow[ml], r1 = srow[ml + 8];
        float g0 = sgt[ml], g1 = sgt[ml + 8];
#pragma unroll
        for (int ni = 0; ni < 4; ni++) {
            int col = n0 + wn * 32 + ni * 8 + lc * 2;
            if (r0 >= 0) {
                atomicAdd(&y[(size_t)r0 * DMODEL + col],     g0 * acc[mi][ni][0]);
                atomicAdd(&y[(size_t)r0 * DMODEL + col + 1], g0 * acc[mi][ni][1]);
            }
            if (r1 >= 0) {
                atomicAdd(&y[(size_t)r1 * DMODEL + col],     g1 * acc[mi][ni][2]);
                atomicAdd(&y[(size_t)r1 * DMODEL + col + 1], g1 * acc[mi][ni][3]);
            }
        }
    }
}

// ---------------- loss ----------------
__global__ void k_loss(const void* lc, float* out, int out_size) {
    float mi = 0.f, ml = 0.f;
#pragma unroll
    for (int e = 0; e < NEXP; e++) { mi += g_imp[e]; ml += g_load[e]; }
    mi *= (1.f / NEXP); ml *= (1.f / NEXP);
    float vi = 0.f, vl = 0.f;
#pragma unroll
    for (int e = 0; e < NEXP; e++) {
        float di = g_imp[e] - mi;  vi += di * di;
        float dl = g_load[e] - ml; vl += dl * dl;
    }
    vi *= (1.f / (NEXP - 1)); vl *= (1.f / (NEXP - 1));
    float cvi = vi / (mi * mi + 1e-10f);
    float cvl = vl / (ml * ml + 1e-10f);
    float coef = 1.f;
    if (lc) {
        int ib = *(const int*)lc;
        float fb = __int_as_float(ib);
        float af = fabsf(fb);
        coef = (af >= 1e-6f && af <= 1e6f) ? fb : (float)ib;
    }
    out[out_size - 1] = (cvi + cvl) * coef;
}

// ---------------- launch ----------------
extern "C" void kernel_launch(void* const* d_in, const int* in_sizes, int n_in,
                              void* d_out, int out_size) {
    const float* x   = (const float*)d_in[0];
    const float* gw1 = (const float*)d_in[1];
    const float* gw2 = (const float*)d_in[2];
    const float* Ws  = (const float*)d_in[3];
    const float* Wt  = (const float*)d_in[4];
    const float* rw  = (const float*)d_in[5];
    const float* rb  = (const float*)d_in[6];
    const void*  lc  = (n_in >= 8) ? d_in[7] : (const void*)0;
    float* out = (float*)d_out;

    k_zero<<<1, 32>>>();
    cudaMemsetAsync(d_out, 0, (size_t)out_size * sizeof(float));
    k_revin<<<NROWS, 128>>>(x, rw, rb);
    k_weff<<<NEXP * DMODEL, 128>>>(Ws, Wt);
    k_gemm_h<<<dim3(NROWS / 128, NHID / 128), 256>>>(x, gw1);
    k_gate<<<NROWS / 8, 256>>>(gw2);
    k_lists<<<NROWS / 256, 256>>>();
    k_gemmE<<<dim3(CAP / 128, DMODEL / 128, NEXP), 256>>>(out);
    k_loss<<<1, 1>>>(lc, out, out_size);
}